// round 3
// baseline (speedup 1.0000x reference)
#include <cuda_runtime.h>
#include <cuda_fp16.h>
#include <cuda_bf16.h>
#include <cstdint>

#define ASZ   8448      // A frag bytes per variant (16 blocks * 528)
#define ABLK  528
#define AOFF2 16896     // 2*ASZ
#define BSZ   16384
#define STG   49664     // AOFF2 + 2*BSZ
#define OFF_LEAF 67584
#define SMEM_DYN 198656
#define PSTR  264       // half elements per P row

static __device__ __nv_bfloat16 g_Wf_hi[262144];
static __device__ __nv_bfloat16 g_Wf_lo[262144];
static __device__ __nv_bfloat16 g_Lf_hi[32768];
static __device__ __nv_bfloat16 g_Lf_lo[32768];

__device__ __forceinline__ uint32_t smem_u32(const void* p) {
    uint32_t a;
    asm("{ .reg .u64 t; cvta.to.shared.u64 t, %1; cvt.u32.u64 %0, t; }" : "=r"(a) : "l"(p));
    return a;
}
__device__ __forceinline__ void cp16(uint32_t dst, const void* src) {
    asm volatile("cp.async.cg.shared.global [%0], [%1], 16;" :: "r"(dst), "l"(src) : "memory");
}
#define CP_COMMIT() asm volatile("cp.async.commit_group;" ::: "memory")
#define CP_WAIT0()  asm volatile("cp.async.wait_group 0;" ::: "memory")

__device__ __forceinline__ void mma_bf16(float* c, const uint32_t* a, uint32_t b0, uint32_t b1) {
    asm volatile("mma.sync.aligned.m16n8k16.row.col.f32.bf16.bf16.f32 "
        "{%0,%1,%2,%3}, {%4,%5,%6,%7}, {%8,%9}, {%0,%1,%2,%3};"
        : "+f"(c[0]), "+f"(c[1]), "+f"(c[2]), "+f"(c[3])
        : "r"(a[0]), "r"(a[1]), "r"(a[2]), "r"(a[3]), "r"(b0), "r"(b1));
}
__device__ __forceinline__ uint32_t pack_bf2(float a, float b) {
    __nv_bfloat162 t = __floats2bfloat162_rn(a, b);
    return *reinterpret_cast<uint32_t*>(&t);
}
__device__ __forceinline__ void split_pk(float pe, float po, uint32_t& hi, uint32_t& lo) {
    __nv_bfloat16 he = __float2bfloat16(pe), ho = __float2bfloat16(po);
    hi = pack_bf2(__bfloat162float(he), __bfloat162float(ho));
    lo = pack_bf2(pe - __bfloat162float(he), po - __bfloat162float(ho));
}

// W[k][n] (k<1024, n<255) -> frag-linear bf16 hi/lo per 32-K chunk
__global__ void prep_w(const float* __restrict__ W) {
    int idx = blockIdx.x * 256 + threadIdx.x;
    int k = idx >> 8, n = idx & 255;
    float v = (n < 255) ? W[k * 255 + n] : 0.0f;
    __nv_bfloat16 h = __float2bfloat16(v);
    __nv_bfloat16 l = __float2bfloat16(v - __bfloat162float(h));
    int chunk = k >> 5, kin = k & 31, s = kin >> 4, kk = kin & 15;
    int nt = n >> 3, tl = (n & 7) * 4 + ((kk >> 1) & 3), rg = kk >> 3, hf = kk & 1;
    int o = chunk * 8192 + s * 4096 + nt * 128 + tl * 4 + rg * 2 + hf;
    g_Wf_hi[o] = h; g_Wf_lo[o] = l;
}
// leaf[k][n] (k<256 leaves, n<128 dout) -> frag-linear
__global__ void prep_leaf(const float* __restrict__ L) {
    int idx = blockIdx.x * 256 + threadIdx.x;
    int k = idx >> 7, n = idx & 127;
    float v = L[k * 128 + n];
    __nv_bfloat16 h = __float2bfloat16(v);
    __nv_bfloat16 l = __float2bfloat16(v - __bfloat162float(h));
    int s = k >> 4, kk = k & 15;
    int nt = n >> 3, tl = (n & 7) * 4 + ((kk >> 1) & 3), rg = kk >> 3, hf = kk & 1;
    int o = s * 2048 + nt * 128 + tl * 4 + rg * 2 + hf;
    g_Lf_hi[o] = h; g_Lf_lo[o] = l;
}
__global__ void init_reg(float* regp) { *regp = 0.0f; }

__device__ __forceinline__ void leaf_pair(const __half* Ph, int j, float& pe, float& po) {
    float pr = 1.0f;
    #pragma unroll
    for (int d = 0; d < 7; d++) {
        int node = (1 << d) - 1 + (j >> (7 - d));
        float pv = __half2float(Ph[node]);
        pr *= ((j >> (6 - d)) & 1) ? pv : (1.0f - pv);
    }
    float p7 = __half2float(Ph[127 + j]);
    pe = pr * (1.0f - p7); po = pr * p7;
}

__global__ void __launch_bounds__(256, 1) tree_main(
    const float* __restrict__ x, const float* __restrict__ bsp,
    float* __restrict__ out, float* __restrict__ regp)
{
    extern __shared__ char smc[];
    __shared__ float s_bias[256];
    __shared__ float s_racc;
    const uint32_t sb = smem_u32(smc);

    const int tid = threadIdx.x, lane = tid & 31, w = tid >> 5;
    const int mwarp = w & 3, nwarp = w >> 2;
    const int mb = mwarp * 32;
    const int m0 = blockIdx.x * 128;

    s_bias[tid] = (tid < 255) ? bsp[tid] : 0.0f;
    if (tid == 0) s_racc = 0.0f;

    float acc[2][16][4] = {};

    // ---------- GEMM1: logits = x @ W (bf16x2 split, 32 K-chunks, double buffer) ----------
    const int r = tid >> 1;                 // row handled by this thread for A staging
    const int koff = (tid & 1) * 16;        // 16 k-elems within chunk
    float4 v[4];

    // prologue: chunk 0 into stage 0
    {
        const float* xp = x + (size_t)(m0 + r) * 1024 + koff;
        #pragma unroll
        for (int i = 0; i < 4; i++) v[i] = *(const float4*)(xp + i * 4);
        #pragma unroll
        for (int i = 0; i < 4; i++) {
            cp16(sb + AOFF2 + (tid + i * 256) * 16, (const char*)g_Wf_hi + (tid + i * 256) * 16);
            cp16(sb + AOFF2 + BSZ + (tid + i * 256) * 16, (const char*)g_Wf_lo + (tid + i * 256) * 16);
        }
        CP_COMMIT();
        const float* fv = (const float*)v;
        #pragma unroll
        for (int q = 0; q < 8; q++) {
            int p = (tid & 1) * 8 + q;
            int s = p >> 3, pp = p & 7;
            int o = (s * 8 + (r >> 4)) * ABLK + (4 * (r & 7) + (pp & 3)) * 16
                    + (((r >> 3) & 1) + ((pp >> 2) << 1)) * 4;
            uint32_t hv, lv;
            split_pk(fv[2 * q], fv[2 * q + 1], hv, lv);
            *(uint32_t*)(smc + o) = hv;
            *(uint32_t*)(smc + o + ASZ) = lv;
        }
    }

    for (int c = 0; c < 32; c++) {
        const int st = c & 1, nst = st ^ 1;
        CP_WAIT0();
        __syncthreads();
        if (c < 31) {
            const float* xp = x + (size_t)(m0 + r) * 1024 + (c + 1) * 32 + koff;
            #pragma unroll
            for (int i = 0; i < 4; i++) v[i] = *(const float4*)(xp + i * 4);
            const char* srcH = (const char*)g_Wf_hi + (c + 1) * 16384;
            const char* srcL = (const char*)g_Wf_lo + (c + 1) * 16384;
            #pragma unroll
            for (int i = 0; i < 4; i++) {
                cp16(sb + nst * STG + AOFF2 + (tid + i * 256) * 16, srcH + (tid + i * 256) * 16);
                cp16(sb + nst * STG + AOFF2 + BSZ + (tid + i * 256) * 16, srcL + (tid + i * 256) * 16);
            }
            CP_COMMIT();
        }
        // MMA on chunk c (2 ksteps)
        #pragma unroll
        for (int s = 0; s < 2; s++) {
            uint32_t ah[2][4], al[2][4];
            #pragma unroll
            for (int mt = 0; mt < 2; mt++) {
                const char* ap = smc + st * STG + (s * 8 + 2 * mwarp + mt) * ABLK + lane * 16;
                *(uint4*)ah[mt] = *(const uint4*)ap;
                *(uint4*)al[mt] = *(const uint4*)(ap + ASZ);
            }
            #pragma unroll
            for (int nt = 0; nt < 16; nt++) {
                const char* bp = smc + st * STG + AOFF2 + (s * 32 + nwarp * 16 + nt) * 256 + lane * 8;
                uint2 bh = *(const uint2*)bp;
                uint2 bl = *(const uint2*)(bp + BSZ);
                #pragma unroll
                for (int mt = 0; mt < 2; mt++) {
                    mma_bf16(acc[mt][nt], ah[mt], bh.x, bh.y);
                    mma_bf16(acc[mt][nt], ah[mt], bl.x, bl.y);
                    mma_bf16(acc[mt][nt], al[mt], bh.x, bh.y);
                }
            }
        }
        if (c < 31) {
            const float* fv = (const float*)v;
            #pragma unroll
            for (int q = 0; q < 8; q++) {
                int p = (tid & 1) * 8 + q;
                int s = p >> 3, pp = p & 7;
                int o = nst * STG + (s * 8 + (r >> 4)) * ABLK + (4 * (r & 7) + (pp & 3)) * 16
                        + (((r >> 3) & 1) + ((pp >> 2) << 1)) * 4;
                uint32_t hv, lv;
                split_pk(fv[2 * q], fv[2 * q + 1], hv, lv);
                *(uint32_t*)(smc + o) = hv;
                *(uint32_t*)(smc + o + ASZ) = lv;
            }
        }
    }
    __syncthreads();   // GEMM1 buffers dead; Psm/leaf regions now safe

    // ---------- prefetch leaf frags (overlap with sigmoid) ----------
    #pragma unroll
    for (int i = 0; i < 16; i++) {
        cp16(sb + OFF_LEAF + (tid + i * 256) * 16, (const char*)g_Lf_hi + (tid + i * 256) * 16);
        cp16(sb + OFF_LEAF + 65536 + (tid + i * 256) * 16, (const char*)g_Lf_lo + (tid + i * 256) * 16);
    }
    CP_COMMIT();

    // ---------- sigmoid + reg term; P -> SMEM fp16 ----------
    float racc = 0.0f;
    __half* Ph0 = (__half*)smc;
    #pragma unroll
    for (int mt = 0; mt < 2; mt++)
        #pragma unroll
        for (int nt = 0; nt < 16; nt++)
            #pragma unroll
            for (int cc = 0; cc < 4; cc++) {
                int row = mb + mt * 16 + (lane >> 2) + ((cc >> 1) << 3);
                int col = nwarp * 128 + nt * 8 + 2 * (lane & 3) + (cc & 1);
                if (col < 255) {
                    float lg = acc[mt][nt][cc] + s_bias[col];
                    float p = 1.0f / (1.0f + __expf(-lg));
                    Ph0[row * PSTR + col] = __float2half(p);
                    int d = 31 - __clz(col + 1);
                    racc += __uint_as_float((uint32_t)(127 - d) << 23) *
                            __logf(fmaxf(p * (1.0f - p), 1e-5f));
                }
            }
    CP_WAIT0();
    __syncthreads();   // Psm + leaf frags visible

    // ---------- tree product (A frags in regs) + GEMM2 ----------
    float acc2[2][8][4] = {};
    #pragma unroll 1
    for (int s = 0; s < 16; s++) {
        uint32_t ah[2][4], al[2][4];
        int jA = 8 * s + (lane & 3), jB = jA + 4;
        #pragma unroll
        for (int mt = 0; mt < 2; mt++) {
            int rL = mb + mt * 16 + (lane >> 2);
            const __half* PhL = Ph0 + rL * PSTR;
            const __half* PhU = PhL + 8 * PSTR;
            float pe, po;
            leaf_pair(PhL, jA, pe, po); split_pk(pe, po, ah[mt][0], al[mt][0]);
            leaf_pair(PhU, jA, pe, po); split_pk(pe, po, ah[mt][1], al[mt][1]);
            leaf_pair(PhL, jB, pe, po); split_pk(pe, po, ah[mt][2], al[mt][2]);
            leaf_pair(PhU, jB, pe, po); split_pk(pe, po, ah[mt][3], al[mt][3]);
        }
        #pragma unroll
        for (int nt = 0; nt < 8; nt++) {
            const char* bp = smc + OFF_LEAF + (s * 16 + nwarp * 8 + nt) * 256 + lane * 8;
            uint2 bh = *(const uint2*)bp;
            uint2 bl = *(const uint2*)(bp + 65536);
            #pragma unroll
            for (int mt = 0; mt < 2; mt++) {
                mma_bf16(acc2[mt][nt], ah[mt], bh.x, bh.y);
                mma_bf16(acc2[mt][nt], ah[mt], bl.x, bl.y);
                mma_bf16(acc2[mt][nt], al[mt], bh.x, bh.y);
            }
        }
    }
    __syncthreads();   // Psm / leaf reads done

    // ---------- output bounce (coalesce) ----------
    float* ob = (float*)smc;    // [128][132]
    #pragma unroll
    for (int mt = 0; mt < 2; mt++)
        #pragma unroll
        for (int nt = 0; nt < 8; nt++)
            #pragma unroll
            for (int cc = 0; cc < 4; cc++) {
                int row = mb + mt * 16 + (lane >> 2) + ((cc >> 1) << 3);
                int col = nwarp * 64 + nt * 8 + 2 * (lane & 3) + (cc & 1);
                ob[row * 132 + col] = acc2[mt][nt][cc];
            }
    __syncthreads();
    #pragma unroll
    for (int i = 0; i < 16; i++) {
        int e = tid + i * 256;
        int rr = e >> 5, cq = e & 31;
        *(float4*)(out + (size_t)(m0 + rr) * 128 + cq * 4) = *(const float4*)(ob + rr * 132 + cq * 4);
    }

    // ---------- regularizer reduction ----------
    #pragma unroll
    for (int o = 16; o; o >>= 1) racc += __shfl_xor_sync(0xFFFFFFFFu, racc, o);
    if (lane == 0) atomicAdd(&s_racc, racc);
    __syncthreads();
    if (tid == 0) atomicAdd(regp, s_racc * (-0.5f / 65536.0f));
}

extern "C" void kernel_launch(void* const* d_in, const int* in_sizes, int n_in,
                              void* d_out, int out_size) {
    const float* x    = (const float*)d_in[0];
    const float* W    = (const float*)d_in[1];
    const float* bsp  = (const float*)d_in[2];
    const float* leaf = (const float*)d_in[3];
    float* out  = (float*)d_out;
    float* regp = out + (out_size - 1);
    cudaFuncSetAttribute(tree_main, cudaFuncAttributeMaxDynamicSharedMemorySize, SMEM_DYN);
    init_reg<<<1, 1>>>(regp);
    prep_w<<<1024, 256>>>(W);
    prep_leaf<<<128, 256>>>(leaf);
    tree_main<<<512, 256, SMEM_DYN>>>(x, bsp, out, regp);
}

// round 4
// speedup vs baseline: 1.1704x; 1.1704x over previous
#include <cuda_runtime.h>
#include <cuda_fp16.h>
#include <cuda_bf16.h>
#include <cstdint>

#define ABLK  528
#define ASZ   4224       // 8 A-blocks * 528B per variant
#define AOFF2 8448       // 2*ASZ
#define BSZ   16384
#define STG   41216      // AOFF2 + 2*BSZ
#define PSTR  264        // half elems per P row
#define OFF_LB 33792     // = 64*264*2 (P bytes); leaf buffers follow
#define SMEM_DYN 99328   // OFF_LB + 2*32768

static __device__ __nv_bfloat16 g_Wf_hi[262144];
static __device__ __nv_bfloat16 g_Wf_lo[262144];
static __device__ __nv_bfloat16 g_Lf_hi[32768];
static __device__ __nv_bfloat16 g_Lf_lo[32768];

__device__ __forceinline__ uint32_t smem_u32(const void* p) {
    uint32_t a;
    asm("{ .reg .u64 t; cvta.to.shared.u64 t, %1; cvt.u32.u64 %0, t; }" : "=r"(a) : "l"(p));
    return a;
}
__device__ __forceinline__ void cp16(uint32_t dst, const void* src) {
    asm volatile("cp.async.cg.shared.global [%0], [%1], 16;" :: "r"(dst), "l"(src) : "memory");
}
#define CP_COMMIT() asm volatile("cp.async.commit_group;" ::: "memory")
#define CP_WAIT0()  asm volatile("cp.async.wait_group 0;" ::: "memory")

__device__ __forceinline__ void mma_bf16(float* c, const uint32_t* a, uint32_t b0, uint32_t b1) {
    asm volatile("mma.sync.aligned.m16n8k16.row.col.f32.bf16.bf16.f32 "
        "{%0,%1,%2,%3}, {%4,%5,%6,%7}, {%8,%9}, {%0,%1,%2,%3};"
        : "+f"(c[0]), "+f"(c[1]), "+f"(c[2]), "+f"(c[3])
        : "r"(a[0]), "r"(a[1]), "r"(a[2]), "r"(a[3]), "r"(b0), "r"(b1));
}
__device__ __forceinline__ uint32_t pack_bf2(float a, float b) {
    __nv_bfloat162 t = __floats2bfloat162_rn(a, b);
    return *reinterpret_cast<uint32_t*>(&t);
}
__device__ __forceinline__ void split_pk(float pe, float po, uint32_t& hi, uint32_t& lo) {
    __nv_bfloat16 he = __float2bfloat16(pe), ho = __float2bfloat16(po);
    hi = pack_bf2(__bfloat162float(he), __bfloat162float(ho));
    lo = pack_bf2(pe - __bfloat162float(he), po - __bfloat162float(ho));
}

// W[k][n] -> frag-linear bf16 hi/lo, 32 K-chunks, paired n-tiles (uint4 = 2 nt frags)
__global__ void prep_w(const float* __restrict__ W) {
    int idx = blockIdx.x * 256 + threadIdx.x;
    int k = idx >> 8, n = idx & 255;
    float v = (n < 255) ? W[k * 255 + n] : 0.0f;
    __nv_bfloat16 h = __float2bfloat16(v);
    __nv_bfloat16 l = __float2bfloat16(v - __bfloat162float(h));
    int chunk = k >> 5, kin = k & 31, s = kin >> 4, kk = kin & 15;
    int nt = n >> 3, pr = nt >> 1, e = nt & 1;
    int tl = (n & 7) * 4 + ((kk >> 1) & 3), rg = kk >> 3, hf = kk & 1;
    int o = chunk * 8192 + s * 4096 + pr * 256 + tl * 8 + e * 4 + rg * 2 + hf;
    g_Wf_hi[o] = h; g_Wf_lo[o] = l;
}
// leaf[k][n] (256 leaves x 128 dout) -> frag-linear, paired n-tiles
__global__ void prep_leaf(const float* __restrict__ L) {
    int idx = blockIdx.x * 256 + threadIdx.x;
    int k = idx >> 7, n = idx & 127;
    float v = L[k * 128 + n];
    __nv_bfloat16 h = __float2bfloat16(v);
    __nv_bfloat16 l = __float2bfloat16(v - __bfloat162float(h));
    int s = k >> 4, kk = k & 15;
    int nt = n >> 3, pr = nt >> 1, e = nt & 1;
    int tl = (n & 7) * 4 + ((kk >> 1) & 3), rg = kk >> 3, hf = kk & 1;
    int o = s * 2048 + pr * 256 + tl * 8 + e * 4 + rg * 2 + hf;
    g_Lf_hi[o] = h; g_Lf_lo[o] = l;
}
__global__ void init_reg(float* regp) { *regp = 0.0f; }

__global__ void __launch_bounds__(256, 2) tree_main(
    const float* __restrict__ x, const float* __restrict__ bsp,
    float* __restrict__ out, float* __restrict__ regp)
{
    extern __shared__ char smc[];
    __shared__ float s_bias[256];
    __shared__ float s_racc;
    const uint32_t sb = smem_u32(smc);

    const int tid = threadIdx.x, lane = tid & 31, w = tid >> 5;
    const int mwarp = w & 3, nwarp = w >> 2;
    const int m0 = blockIdx.x * 64;

    s_bias[tid] = (tid < 255) ? bsp[tid] : 0.0f;
    if (tid == 0) s_racc = 0.0f;

    float acc[16][4] = {};

    const int r = tid >> 2;             // staging row 0..63
    const int ko = (tid & 3) * 8;       // 8 consecutive k per thread

    // ---- prologue: chunk 0 ----
    {
        const float* xp = x + (size_t)(m0 + r) * 1024 + ko;
        float fv[8];
        *(float4*)(fv)     = *(const float4*)xp;
        *(float4*)(fv + 4) = *(const float4*)(xp + 4);
        #pragma unroll
        for (int i = 0; i < 4; i++) {
            cp16(sb + AOFF2 + (tid + i * 256) * 16, (const char*)g_Wf_hi + (tid + i * 256) * 16);
            cp16(sb + AOFF2 + BSZ + (tid + i * 256) * 16, (const char*)g_Wf_lo + (tid + i * 256) * 16);
        }
        CP_COMMIT();
        #pragma unroll
        for (int q = 0; q < 4; q++) {
            int p = (tid & 3) * 4 + q;
            int s = p >> 3, pp = p & 7;
            int o = (s * 4 + (r >> 4)) * ABLK + (4 * (r & 7) + (pp & 3)) * 16
                    + (((r >> 3) & 1) + ((pp >> 2) << 1)) * 4;
            uint32_t hv, lv;
            split_pk(fv[2 * q], fv[2 * q + 1], hv, lv);
            *(uint32_t*)(smc + o) = hv;
            *(uint32_t*)(smc + o + ASZ) = lv;
        }
    }

    // ---- GEMM1: 32 K-chunks, double-buffered ----
    for (int c = 0; c < 32; c++) {
        const int st = c & 1, nst = st ^ 1;
        CP_WAIT0();
        __syncthreads();
        float fv[8];
        if (c < 31) {
            const float* xp = x + (size_t)(m0 + r) * 1024 + (c + 1) * 32 + ko;
            *(float4*)(fv)     = *(const float4*)xp;
            *(float4*)(fv + 4) = *(const float4*)(xp + 4);
            const char* srcH = (const char*)g_Wf_hi + (c + 1) * 16384;
            const char* srcL = (const char*)g_Wf_lo + (c + 1) * 16384;
            #pragma unroll
            for (int i = 0; i < 4; i++) {
                cp16(sb + nst * STG + AOFF2 + (tid + i * 256) * 16, srcH + (tid + i * 256) * 16);
                cp16(sb + nst * STG + AOFF2 + BSZ + (tid + i * 256) * 16, srcL + (tid + i * 256) * 16);
            }
            CP_COMMIT();
        }
        #pragma unroll
        for (int s = 0; s < 2; s++) {
            uint32_t ah[4], al[4];
            const char* ap = smc + st * STG + (s * 4 + mwarp) * ABLK + lane * 16;
            *(uint4*)ah = *(const uint4*)ap;
            *(uint4*)al = *(const uint4*)(ap + ASZ);
            #pragma unroll
            for (int ntp = 0; ntp < 8; ntp++) {
                const char* bp = smc + st * STG + AOFF2 + s * 8192 + (nwarp * 8 + ntp) * 512 + lane * 16;
                uint4 bh = *(const uint4*)bp;
                uint4 bl = *(const uint4*)(bp + BSZ);
                mma_bf16(acc[2 * ntp],     ah, bh.x, bh.y);
                mma_bf16(acc[2 * ntp],     ah, bl.x, bl.y);
                mma_bf16(acc[2 * ntp],     al, bh.x, bh.y);
                mma_bf16(acc[2 * ntp + 1], ah, bh.z, bh.w);
                mma_bf16(acc[2 * ntp + 1], ah, bl.z, bl.w);
                mma_bf16(acc[2 * ntp + 1], al, bh.z, bh.w);
            }
        }
        if (c < 31) {
            #pragma unroll
            for (int q = 0; q < 4; q++) {
                int p = (tid & 3) * 4 + q;
                int s = p >> 3, pp = p & 7;
                int o = nst * STG + (s * 4 + (r >> 4)) * ABLK + (4 * (r & 7) + (pp & 3)) * 16
                        + (((r >> 3) & 1) + ((pp >> 2) << 1)) * 4;
                uint32_t hv, lv;
                split_pk(fv[2 * q], fv[2 * q + 1], hv, lv);
                *(uint32_t*)(smc + o) = hv;
                *(uint32_t*)(smc + o + ASZ) = lv;
            }
        }
    }
    __syncthreads();   // GEMM1 regions dead

    // ---- prefetch leaf quarter 0, then sigmoid + reg; P -> SMEM fp16 ----
    #pragma unroll
    for (int i = 0; i < 4; i++) {
        cp16(sb + OFF_LB + (tid + i * 256) * 16, (const char*)g_Lf_hi + (tid + i * 256) * 16);
        cp16(sb + OFF_LB + 16384 + (tid + i * 256) * 16, (const char*)g_Lf_lo + (tid + i * 256) * 16);
    }
    CP_COMMIT();

    float racc = 0.0f;
    __half* Ph0 = (__half*)smc;
    #pragma unroll
    for (int nt = 0; nt < 16; nt++)
        #pragma unroll
        for (int cc = 0; cc < 4; cc++) {
            int row = mwarp * 16 + (lane >> 2) + ((cc >> 1) << 3);
            int col = nwarp * 128 + nt * 8 + 2 * (lane & 3) + (cc & 1);
            if (col < 255) {
                float lg = acc[nt][cc] + s_bias[col];
                float p = 1.0f / (1.0f + __expf(-lg));
                Ph0[row * PSTR + col] = __float2half(p);
                int d = 31 - __clz(col + 1);
                racc += __uint_as_float((uint32_t)(127 - d) << 23) *
                        __logf(fmaxf(p * (1.0f - p), 1e-5f));
            }
        }

    // ---- GEMM2: tree-product A frags + leaf quarters (double-buffered) ----
    float acc2[8][4] = {};
    const int la = lane & 3;
    #pragma unroll 1
    for (int qq = 0; qq < 4; qq++) {
        CP_WAIT0();
        __syncthreads();
        if (qq < 3) {
            uint32_t db = sb + OFF_LB + ((qq + 1) & 1) * 32768;
            const char* sh = (const char*)(g_Lf_hi + (qq + 1) * 8192);
            const char* sl = (const char*)(g_Lf_lo + (qq + 1) * 8192);
            #pragma unroll
            for (int i = 0; i < 4; i++) {
                cp16(db + (tid + i * 256) * 16, sh + (tid + i * 256) * 16);
                cp16(db + 16384 + (tid + i * 256) * 16, sl + (tid + i * 256) * 16);
            }
            CP_COMMIT();
        }
        const char* LB = smc + OFF_LB + (qq & 1) * 32768;
        #pragma unroll
        for (int sl2 = 0; sl2 < 4; sl2++) {
            int s = qq * 4 + sl2;
            int jA = 8 * s + la, jB = jA + 4;
            uint32_t ah[4], al4[4];
            #pragma unroll
            for (int rr = 0; rr < 2; rr++) {
                int row = mwarp * 16 + (lane >> 2) + rr * 8;
                const __half* Ph = Ph0 + row * PSTR;
                float pv, pre;
                pv = __half2float(Ph[s >> 4]);     pre  = ((s >> 3) & 1) ? pv : 1.0f - pv;
                pv = __half2float(Ph[1 + (s >> 3)]); pre *= ((s >> 2) & 1) ? pv : 1.0f - pv;
                pv = __half2float(Ph[3 + (s >> 2)]); pre *= ((s >> 1) & 1) ? pv : 1.0f - pv;
                pv = __half2float(Ph[7 + (s >> 1)]); pre *= (s & 1) ? pv : 1.0f - pv;
                float p4 = __half2float(Ph[15 + s]);
                float preA = pre * (1.0f - p4), preB = pre * p4;
                int b5 = (la >> 1) & 1, b6 = la & 1;
                float p5a = __half2float(Ph[31 + 2 * s]);
                float p5b = __half2float(Ph[31 + 2 * s + 1]);
                preA *= b5 ? p5a : 1.0f - p5a;
                preB *= b5 ? p5b : 1.0f - p5b;
                float p6a = __half2float(Ph[63 + (jA >> 1)]);
                float p6b = __half2float(Ph[63 + (jB >> 1)]);
                preA *= b6 ? p6a : 1.0f - p6a;
                preB *= b6 ? p6b : 1.0f - p6b;
                float p7a = __half2float(Ph[127 + jA]);
                float p7b = __half2float(Ph[127 + jB]);
                split_pk(preA * (1.0f - p7a), preA * p7a, ah[rr], al4[rr]);
                split_pk(preB * (1.0f - p7b), preB * p7b, ah[2 + rr], al4[2 + rr]);
            }
            #pragma unroll
            for (int ntp = 0; ntp < 4; ntp++) {
                const char* bp = LB + sl2 * 4096 + (nwarp * 4 + ntp) * 512 + lane * 16;
                uint4 bh = *(const uint4*)bp;
                uint4 bl = *(const uint4*)(bp + 16384);
                mma_bf16(acc2[2 * ntp],     ah, bh.x, bh.y);
                mma_bf16(acc2[2 * ntp],     ah, bl.x, bl.y);
                mma_bf16(acc2[2 * ntp],     al4, bh.x, bh.y);
                mma_bf16(acc2[2 * ntp + 1], ah, bh.z, bh.w);
                mma_bf16(acc2[2 * ntp + 1], ah, bl.z, bl.w);
                mma_bf16(acc2[2 * ntp + 1], al4, bh.z, bh.w);
            }
        }
    }
    __syncthreads();   // all P reads done

    // ---- output bounce (coalesce) ----
    float* ob = (float*)smc;    // [64][132]
    #pragma unroll
    for (int nt = 0; nt < 8; nt++)
        #pragma unroll
        for (int cc = 0; cc < 4; cc++) {
            int row = mwarp * 16 + (lane >> 2) + ((cc >> 1) << 3);
            int col = nwarp * 64 + nt * 8 + 2 * (lane & 3) + (cc & 1);
            ob[row * 132 + col] = acc2[nt][cc];
        }
    __syncthreads();
    #pragma unroll
    for (int i = 0; i < 8; i++) {
        int e = tid + i * 256;
        int rr = e >> 5, cq = e & 31;
        *(float4*)(out + (size_t)(m0 + rr) * 128 + cq * 4) = *(const float4*)(ob + rr * 132 + cq * 4);
    }

    // ---- regularizer reduction ----
    #pragma unroll
    for (int o = 16; o; o >>= 1) racc += __shfl_xor_sync(0xFFFFFFFFu, racc, o);
    if (lane == 0) atomicAdd(&s_racc, racc);
    __syncthreads();
    if (tid == 0) atomicAdd(regp, s_racc * (-0.5f / 65536.0f));
}

extern "C" void kernel_launch(void* const* d_in, const int* in_sizes, int n_in,
                              void* d_out, int out_size) {
    const float* x    = (const float*)d_in[0];
    const float* W    = (const float*)d_in[1];
    const float* bsp  = (const float*)d_in[2];
    const float* leaf = (const float*)d_in[3];
    float* out  = (float*)d_out;
    float* regp = out + (out_size - 1);
    cudaFuncSetAttribute(tree_main, cudaFuncAttributeMaxDynamicSharedMemorySize, SMEM_DYN);
    init_reg<<<1, 1>>>(regp);
    prep_w<<<1024, 256>>>(W);
    prep_leaf<<<128, 256>>>(leaf);
    tree_main<<<1024, 256, SMEM_DYN>>>(x, bsp, out, regp);
}

// round 6
// speedup vs baseline: 1.2716x; 1.0865x over previous
#include <cuda_runtime.h>
#include <cuda_fp16.h>
#include <cuda_bf16.h>
#include <cstdint>

#define ABLK  528
#define ASZ   4224       // 8 A-blocks * 528B per variant
#define AOFF2 8448       // 2*ASZ
#define BSZ   16384
#define STG   41216      // AOFF2 + 2*BSZ
#define PSTR  264        // half elems per P row
#define OFF_LB 33792     // = 64*264*2 (P bytes); leaf buffers follow
#define SMEM_DYN 99328   // OFF_LB + 2*32768

static __device__ __nv_bfloat16 g_Wf_hi[262144];
static __device__ __nv_bfloat16 g_Wf_lo[262144];
static __device__ __nv_bfloat16 g_Lf_hi[32768];
static __device__ __nv_bfloat16 g_Lf_lo[32768];

__device__ __forceinline__ uint32_t smem_u32(const void* p) {
    uint32_t a;
    asm("{ .reg .u64 t; cvta.to.shared.u64 t, %1; cvt.u32.u64 %0, t; }" : "=r"(a) : "l"(p));
    return a;
}
__device__ __forceinline__ void cp16(uint32_t dst, const void* src) {
    asm volatile("cp.async.cg.shared.global [%0], [%1], 16;" :: "r"(dst), "l"(src) : "memory");
}
#define CP_COMMIT() asm volatile("cp.async.commit_group;" ::: "memory")
#define CP_WAIT0()  asm volatile("cp.async.wait_group 0;" ::: "memory")

__device__ __forceinline__ void mma_bf16(float* c, const uint32_t* a, uint32_t b0, uint32_t b1) {
    asm volatile("mma.sync.aligned.m16n8k16.row.col.f32.bf16.bf16.f32 "
        "{%0,%1,%2,%3}, {%4,%5,%6,%7}, {%8,%9}, {%0,%1,%2,%3};"
        : "+f"(c[0]), "+f"(c[1]), "+f"(c[2]), "+f"(c[3])
        : "r"(a[0]), "r"(a[1]), "r"(a[2]), "r"(a[3]), "r"(b0), "r"(b1));
}
__device__ __forceinline__ uint32_t pack_bf2(float a, float b) {
    __nv_bfloat162 t = __floats2bfloat162_rn(a, b);
    return *reinterpret_cast<uint32_t*>(&t);
}
__device__ __forceinline__ void split_pk(float pe, float po, uint32_t& hi, uint32_t& lo) {
    __nv_bfloat16 he = __float2bfloat16(pe), ho = __float2bfloat16(po);
    hi = pack_bf2(__bfloat162float(he), __bfloat162float(ho));
    lo = pack_bf2(pe - __bfloat162float(he), po - __bfloat162float(ho));
}

// W[k][n] -> frag-linear bf16 hi/lo, 32 K-chunks, paired n-tiles (uint4 = 2 nt frags)
__global__ void prep_w(const float* __restrict__ W) {
    int idx = blockIdx.x * 256 + threadIdx.x;
    int k = idx >> 8, n = idx & 255;
    float v = (n < 255) ? W[k * 255 + n] : 0.0f;
    __nv_bfloat16 h = __float2bfloat16(v);
    __nv_bfloat16 l = __float2bfloat16(v - __bfloat162float(h));
    int chunk = k >> 5, kin = k & 31, s = kin >> 4, kk = kin & 15;
    int nt = n >> 3, pr = nt >> 1, e = nt & 1;
    int tl = (n & 7) * 4 + ((kk >> 1) & 3), rg = kk >> 3, hf = kk & 1;
    int o = chunk * 8192 + s * 4096 + pr * 256 + tl * 8 + e * 4 + rg * 2 + hf;
    g_Wf_hi[o] = h; g_Wf_lo[o] = l;
}
// leaf[k][n] (256 leaves x 128 dout) -> frag-linear, paired n-tiles
__global__ void prep_leaf(const float* __restrict__ L) {
    int idx = blockIdx.x * 256 + threadIdx.x;
    int k = idx >> 7, n = idx & 127;
    float v = L[k * 128 + n];
    __nv_bfloat16 h = __float2bfloat16(v);
    __nv_bfloat16 l = __float2bfloat16(v - __bfloat162float(h));
    int s = k >> 4, kk = k & 15;
    int nt = n >> 3, pr = nt >> 1, e = nt & 1;
    int tl = (n & 7) * 4 + ((kk >> 1) & 3), rg = kk >> 3, hf = kk & 1;
    int o = s * 2048 + pr * 256 + tl * 8 + e * 4 + rg * 2 + hf;
    g_Lf_hi[o] = h; g_Lf_lo[o] = l;
}
__global__ void init_reg(float* regp) { *regp = 0.0f; }

__global__ void __launch_bounds__(256, 2) tree_main(
    const float* __restrict__ x, const float* __restrict__ bsp,
    float* __restrict__ out, float* __restrict__ regp)
{
    extern __shared__ char smc[];
    __shared__ float s_bias[256];
    __shared__ float s_racc;
    const uint32_t sb = smem_u32(smc);

    const int tid = threadIdx.x, lane = tid & 31, w = tid >> 5;
    const int mwarp = w & 1, nwarp = w >> 1;          // 32-row x 64-col warp tile
    const int m0 = blockIdx.x * 64;

    s_bias[tid] = (tid < 255) ? bsp[tid] : 0.0f;
    if (tid == 0) s_racc = 0.0f;

    float acc[2][8][4] = {};

    const int r = tid >> 2;             // staging row 0..63
    const int ko = (tid & 3) * 8;       // 8 consecutive k per thread

    // ---- prologue: chunk 0 ----
    {
        const float* xp = x + (size_t)(m0 + r) * 1024 + ko;
        float fv[8];
        *(float4*)(fv)     = *(const float4*)xp;
        *(float4*)(fv + 4) = *(const float4*)(xp + 4);
        #pragma unroll
        for (int i = 0; i < 4; i++) {
            cp16(sb + AOFF2 + (tid + i * 256) * 16, (const char*)g_Wf_hi + (tid + i * 256) * 16);
            cp16(sb + AOFF2 + BSZ + (tid + i * 256) * 16, (const char*)g_Wf_lo + (tid + i * 256) * 16);
        }
        CP_COMMIT();
        #pragma unroll
        for (int q = 0; q < 4; q++) {
            int p = (tid & 3) * 4 + q;
            int s = p >> 3, pp = p & 7;
            int o = (s * 4 + (r >> 4)) * ABLK + (4 * (r & 7) + (pp & 3)) * 16
                    + (((r >> 3) & 1) + ((pp >> 2) << 1)) * 4;
            uint32_t hv, lv;
            split_pk(fv[2 * q], fv[2 * q + 1], hv, lv);
            *(uint32_t*)(smc + o) = hv;
            *(uint32_t*)(smc + o + ASZ) = lv;
        }
    }

    // ---- GEMM1: 32 K-chunks, double-buffered ----
    for (int c = 0; c < 32; c++) {
        const int st = c & 1, nst = st ^ 1;
        CP_WAIT0();
        __syncthreads();
        float fv[8];
        if (c < 31) {
            const float* xp = x + (size_t)(m0 + r) * 1024 + (c + 1) * 32 + ko;
            *(float4*)(fv)     = *(const float4*)xp;
            *(float4*)(fv + 4) = *(const float4*)(xp + 4);
            const char* srcH = (const char*)g_Wf_hi + (c + 1) * 16384;
            const char* srcL = (const char*)g_Wf_lo + (c + 1) * 16384;
            #pragma unroll
            for (int i = 0; i < 4; i++) {
                cp16(sb + nst * STG + AOFF2 + (tid + i * 256) * 16, srcH + (tid + i * 256) * 16);
                cp16(sb + nst * STG + AOFF2 + BSZ + (tid + i * 256) * 16, srcL + (tid + i * 256) * 16);
            }
            CP_COMMIT();
        }
        #pragma unroll
        for (int s = 0; s < 2; s++) {
            uint32_t ah[2][4], al[2][4];
            #pragma unroll
            for (int mt = 0; mt < 2; mt++) {
                const char* ap = smc + st * STG + (s * 4 + mwarp * 2 + mt) * ABLK + lane * 16;
                *(uint4*)ah[mt] = *(const uint4*)ap;
                *(uint4*)al[mt] = *(const uint4*)(ap + ASZ);
            }
            #pragma unroll
            for (int ntp = 0; ntp < 4; ntp++) {
                const char* bp = smc + st * STG + AOFF2 + s * 8192 + (nwarp * 4 + ntp) * 512 + lane * 16;
                uint4 bh = *(const uint4*)bp;
                uint4 bl = *(const uint4*)(bp + BSZ);
                #pragma unroll
                for (int mt = 0; mt < 2; mt++) {
                    mma_bf16(acc[mt][2 * ntp],     ah[mt], bh.x, bh.y);
                    mma_bf16(acc[mt][2 * ntp],     ah[mt], bl.x, bl.y);
                    mma_bf16(acc[mt][2 * ntp],     al[mt], bh.x, bh.y);
                    mma_bf16(acc[mt][2 * ntp + 1], ah[mt], bh.z, bh.w);
                    mma_bf16(acc[mt][2 * ntp + 1], ah[mt], bl.z, bl.w);
                    mma_bf16(acc[mt][2 * ntp + 1], al[mt], bh.z, bh.w);
                }
            }
        }
        if (c < 31) {
            #pragma unroll
            for (int q = 0; q < 4; q++) {
                int p = (tid & 3) * 4 + q;
                int s = p >> 3, pp = p & 7;
                int o = nst * STG + (s * 4 + (r >> 4)) * ABLK + (4 * (r & 7) + (pp & 3)) * 16
                        + (((r >> 3) & 1) + ((pp >> 2) << 1)) * 4;
                uint32_t hv, lv;
                split_pk(fv[2 * q], fv[2 * q + 1], hv, lv);
                *(uint32_t*)(smc + o) = hv;
                *(uint32_t*)(smc + o + ASZ) = lv;
            }
        }
    }
    __syncthreads();   // GEMM1 regions dead

    // ---- prefetch leaf quarter 0, then sigmoid + reg; P -> SMEM fp16 ----
    #pragma unroll
    for (int i = 0; i < 4; i++) {
        cp16(sb + OFF_LB + (tid + i * 256) * 16, (const char*)g_Lf_hi + (tid + i * 256) * 16);
        cp16(sb + OFF_LB + 16384 + (tid + i * 256) * 16, (const char*)g_Lf_lo + (tid + i * 256) * 16);
    }
    CP_COMMIT();

    float racc = 0.0f;
    __half* Ph0 = (__half*)smc;
    #pragma unroll
    for (int mt = 0; mt < 2; mt++)
        #pragma unroll
        for (int nt = 0; nt < 8; nt++)
            #pragma unroll
            for (int cc = 0; cc < 4; cc++) {
                int row = mwarp * 32 + mt * 16 + (lane >> 2) + ((cc >> 1) << 3);
                int col = nwarp * 64 + nt * 8 + 2 * (lane & 3) + (cc & 1);
                if (col < 255) {
                    float lg = acc[mt][nt][cc] + s_bias[col];
                    float p = 1.0f / (1.0f + __expf(-lg));
                    Ph0[row * PSTR + col] = __float2half(p);
                    int d = 31 - __clz(col + 1);
                    racc += __uint_as_float((uint32_t)(127 - d) << 23) *
                            __logf(fmaxf(p * (1.0f - p), 1e-5f));
                }
            }

    // ---- GEMM2: tree-product A frags + leaf quarters (double-buffered) ----
    float acc2[8][4] = {};
    const int mwarp2 = w & 3, nwarp2 = w >> 2;
    const int la = lane & 3;
    #pragma unroll 1
    for (int qq = 0; qq < 4; qq++) {
        CP_WAIT0();
        __syncthreads();
        if (qq < 3) {
            uint32_t db = sb + OFF_LB + ((qq + 1) & 1) * 32768;
            const char* sh = (const char*)(g_Lf_hi + (qq + 1) * 8192);
            const char* sl = (const char*)(g_Lf_lo + (qq + 1) * 8192);
            #pragma unroll
            for (int i = 0; i < 4; i++) {
                cp16(db + (tid + i * 256) * 16, sh + (tid + i * 256) * 16);
                cp16(db + 16384 + (tid + i * 256) * 16, sl + (tid + i * 256) * 16);
            }
            CP_COMMIT();
        }
        const char* LB = smc + OFF_LB + (qq & 1) * 32768;
        #pragma unroll
        for (int sl2 = 0; sl2 < 4; sl2++) {
            int s = qq * 4 + sl2;
            int jA = 8 * s + la, jB = jA + 4;
            uint32_t ah[4], al4[4];
            #pragma unroll
            for (int rr = 0; rr < 2; rr++) {
                int row = mwarp2 * 16 + (lane >> 2) + rr * 8;
                const __half* Ph = Ph0 + row * PSTR;
                float pv, pre;
                pv = __half2float(Ph[s >> 4]);       pre  = ((s >> 3) & 1) ? pv : 1.0f - pv;
                pv = __half2float(Ph[1 + (s >> 3)]); pre *= ((s >> 2) & 1) ? pv : 1.0f - pv;
                pv = __half2float(Ph[3 + (s >> 2)]); pre *= ((s >> 1) & 1) ? pv : 1.0f - pv;
                pv = __half2float(Ph[7 + (s >> 1)]); pre *= (s & 1) ? pv : 1.0f - pv;
                float p4 = __half2float(Ph[15 + s]);
                float preA = pre * (1.0f - p4), preB = pre * p4;
                int b5 = (la >> 1) & 1, b6 = la & 1;
                float p5a = __half2float(Ph[31 + 2 * s]);
                float p5b = __half2float(Ph[31 + 2 * s + 1]);
                preA *= b5 ? p5a : 1.0f - p5a;
                preB *= b5 ? p5b : 1.0f - p5b;
                float p6a = __half2float(Ph[63 + (jA >> 1)]);
                float p6b = __half2float(Ph[63 + (jB >> 1)]);
                preA *= b6 ? p6a : 1.0f - p6a;
                preB *= b6 ? p6b : 1.0f - p6b;
                float p7a = __half2float(Ph[127 + jA]);
                float p7b = __half2float(Ph[127 + jB]);
                split_pk(preA * (1.0f - p7a), preA * p7a, ah[rr], al4[rr]);
                split_pk(preB * (1.0f - p7b), preB * p7b, ah[2 + rr], al4[2 + rr]);
            }
            #pragma unroll
            for (int ntp = 0; ntp < 4; ntp++) {
                const char* bp = LB + sl2 * 4096 + (nwarp2 * 4 + ntp) * 512 + lane * 16;
                uint4 bh = *(const uint4*)bp;
                uint4 bl = *(const uint4*)(bp + 16384);
                mma_bf16(acc2[2 * ntp],     ah, bh.x, bh.y);
                mma_bf16(acc2[2 * ntp],     ah, bl.x, bl.y);
                mma_bf16(acc2[2 * ntp],     al4, bh.x, bh.y);
                mma_bf16(acc2[2 * ntp + 1], ah, bh.z, bh.w);
                mma_bf16(acc2[2 * ntp + 1], ah, bl.z, bl.w);
                mma_bf16(acc2[2 * ntp + 1], al4, bh.z, bh.w);
            }
        }
    }
    __syncthreads();   // all P reads done

    // ---- output bounce (coalesce) ----
    float* ob = (float*)smc;    // [64][132]
    #pragma unroll
    for (int nt = 0; nt < 8; nt++)
        #pragma unroll
        for (int cc = 0; cc < 4; cc++) {
            int row = mwarp2 * 16 + (lane >> 2) + ((cc >> 1) << 3);
            int col = nwarp2 * 64 + nt * 8 + 2 * (lane & 3) + (cc & 1);
            ob[row * 132 + col] = acc2[nt][cc];
        }
    __syncthreads();
    #pragma unroll
    for (int i = 0; i < 8; i++) {
        int e = tid + i * 256;
        int rr = e >> 5, cq = e & 31;
        *(float4*)(out + (size_t)(m0 + rr) * 128 + cq * 4) = *(const float4*)(ob + rr * 132 + cq * 4);
    }

    // ---- regularizer reduction ----
    #pragma unroll
    for (int o = 16; o; o >>= 1) racc += __shfl_xor_sync(0xFFFFFFFFu, racc, o);
    if (lane == 0) atomicAdd(&s_racc, racc);
    __syncthreads();
    if (tid == 0) atomicAdd(regp, s_racc * (-0.5f / 65536.0f));
}

extern "C" void kernel_launch(void* const* d_in, const int* in_sizes, int n_in,
                              void* d_out, int out_size) {
    const float* x    = (const float*)d_in[0];
    const float* W    = (const float*)d_in[1];
    const float* bsp  = (const float*)d_in[2];
    const float* leaf = (const float*)d_in[3];
    float* out  = (float*)d_out;
    float* regp = out + (out_size - 1);
    cudaFuncSetAttribute(tree_main, cudaFuncAttributeMaxDynamicSharedMemorySize, SMEM_DYN);
    init_reg<<<1, 1>>>(regp);
    prep_w<<<1024, 256>>>(W);
    prep_leaf<<<128, 256>>>(leaf);
    tree_main<<<1024, 256, SMEM_DYN>>>(x, bsp, out, regp);
}